// round 3
// baseline (speedup 1.0000x reference)
#include <cuda_runtime.h>

#define N_ROWS    65536
#define N_CLASSES 1000
#define N_F4      250          // 1000 / 4
#define EPS_F     1e-9f
#define NORM_FAC  0.1f
#define WARPS_PER_BLOCK 8
#define N_BLOCKS  888                     // 148 SMs * 6 CTAs/SM — one wave
#define TOTAL_WARPS (N_BLOCKS * WARPS_PER_BLOCK)   // 7104

__global__ __launch_bounds__(WARPS_PER_BLOCK * 32, 6)
void cosine_loss_kernel(const float* __restrict__ pred,
                        const long long* __restrict__ target,
                        float* __restrict__ out) {
    const int warp  = threadIdx.x >> 5;
    const int lane  = threadIdx.x & 31;
    const int gwarp = blockIdx.x * WARPS_PER_BLOCK + warp;

    float loss_acc = 0.0f;   // per-thread partial (lane-replicated after shuffles)

    for (int row = gwarp; row < N_ROWS; row += TOTAL_WARPS) {
        const float4* __restrict__ rowp =
            reinterpret_cast<const float4*>(pred + (size_t)row * N_CLASSES);

        const int t = (int)target[row];
        const int t_f4   = t >> 2;
        const int t_comp = t & 3;

        // Front-batch ALL 8 loads (MLP=8). Out-of-range lanes clamp to index
        // 249 — same sector as lane 25's load, no extra DRAM traffic.
        float4 v[8];
        #pragma unroll
        for (int j = 0; j < 8; j++) {
            const int f4  = lane + 32 * j;
            const int f4c = (f4 < N_F4) ? f4 : (N_F4 - 1);
            v[j] = __ldcs(rowp + f4c);
        }

        float sumsq    = 0.0f;
        float gathered = 0.0f;

        #pragma unroll
        for (int j = 0; j < 8; j++) {
            const int f4 = lane + 32 * j;
            const float4 w = v[j];
            if (f4 < N_F4) {
                sumsq += w.x * w.x + w.y * w.y + w.z * w.z + w.w * w.w;
            }
            if (f4 == t_f4) {
                gathered = (t_comp == 0) ? w.x :
                           (t_comp == 1) ? w.y :
                           (t_comp == 2) ? w.z : w.w;
            }
        }

        #pragma unroll
        for (int off = 16; off > 0; off >>= 1) {
            sumsq    += __shfl_xor_sync(0xffffffffu, sumsq, off);
            gathered += __shfl_xor_sync(0xffffffffu, gathered, off);
        }

        const float norm = sqrtf(sumsq);
        const float d    = 1.0f - norm;
        loss_acc += -gathered / (norm + EPS_F) + NORM_FAC * d * d;
    }

    // block reduction: lane 0 of each warp holds the warp's row-sum
    __shared__ float s_partial[WARPS_PER_BLOCK];
    if (lane == 0) s_partial[warp] = loss_acc * (1.0f / (float)N_ROWS);
    __syncthreads();

    if (threadIdx.x == 0) {
        float acc = 0.0f;
        #pragma unroll
        for (int i = 0; i < WARPS_PER_BLOCK; i++) acc += s_partial[i];
        atomicAdd(out, acc);
    }
}

extern "C" void kernel_launch(void* const* d_in, const int* in_sizes, int n_in,
                              void* d_out, int out_size) {
    const float*     pred   = (const float*)d_in[0];
    const long long* target = (const long long*)d_in[1];
    float*           out    = (float*)d_out;

    // graph memset node: zero the fp32 accumulator (0.0f == all-zero bits)
    cudaMemsetAsync(out, 0, sizeof(float));

    cosine_loss_kernel<<<N_BLOCKS, WARPS_PER_BLOCK * 32>>>(pred, target, out);
}

// round 4
// speedup vs baseline: 1.0376x; 1.0376x over previous
#include <cuda_runtime.h>

#define N_ROWS    65536
#define N_CLASSES 1000
#define N_F4      250          // 1000 / 4
#define EPS_F     1e-9f
#define NORM_FAC  0.1f
#define WARPS_PER_BLOCK 8

__global__ __launch_bounds__(WARPS_PER_BLOCK * 32, 7)   // force regs<=36 -> 7 CTAs/SM
void cosine_loss_kernel(const float* __restrict__ pred,
                        const long long* __restrict__ target,
                        float* __restrict__ out) {
    const int warp = threadIdx.x >> 5;
    const int lane = threadIdx.x & 31;
    const int row  = blockIdx.x * WARPS_PER_BLOCK + warp;

    const float4* __restrict__ rowp =
        reinterpret_cast<const float4*>(pred + (size_t)row * N_CLASSES);

    const int t = (int)target[row];
    const int t_f4   = t >> 2;
    const int t_comp = t & 3;

    // Front-batch ALL 8 loads (MLP=8). Out-of-range lanes (j==7, lane>=26)
    // clamp to index 249 — same sector as lane 25's load, no extra traffic.
    float4 v[8];
    #pragma unroll
    for (int j = 0; j < 8; j++) {
        const int f4  = lane + 32 * j;
        const int f4c = min(f4, N_F4 - 1);
        v[j] = __ldcs(rowp + f4c);
    }

    float sumsq    = 0.0f;
    float gathered = 0.0f;

    #pragma unroll
    for (int j = 0; j < 8; j++) {
        const int f4 = lane + 32 * j;
        const float4 w = v[j];
        if (f4 < N_F4) {
            sumsq += w.x * w.x + w.y * w.y + w.z * w.z + w.w * w.w;
        }
        if (f4 == t_f4) {
            gathered = (t_comp == 0) ? w.x :
                       (t_comp == 1) ? w.y :
                       (t_comp == 2) ? w.z : w.w;
        }
    }

    #pragma unroll
    for (int off = 16; off > 0; off >>= 1) {
        sumsq    += __shfl_xor_sync(0xffffffffu, sumsq, off);
        gathered += __shfl_xor_sync(0xffffffffu, gathered, off);
    }

    __shared__ float s_partial[WARPS_PER_BLOCK];
    if (lane == 0) {
        const float norm = sqrtf(sumsq);
        const float d    = 1.0f - norm;
        s_partial[warp] = (-gathered / (norm + EPS_F) + NORM_FAC * d * d)
                          * (1.0f / (float)N_ROWS);
    }
    __syncthreads();

    if (threadIdx.x == 0) {
        float acc = 0.0f;
        #pragma unroll
        for (int i = 0; i < WARPS_PER_BLOCK; i++) acc += s_partial[i];
        atomicAdd(out, acc);
    }
}

extern "C" void kernel_launch(void* const* d_in, const int* in_sizes, int n_in,
                              void* d_out, int out_size) {
    const float*     pred   = (const float*)d_in[0];
    const long long* target = (const long long*)d_in[1];
    float*           out    = (float*)d_out;

    // graph memset node: zero the fp32 accumulator (0.0f == all-zero bits)
    cudaMemsetAsync(out, 0, sizeof(float));

    const int n_blocks = N_ROWS / WARPS_PER_BLOCK;   // 8192
    cosine_loss_kernel<<<n_blocks, WARPS_PER_BLOCK * 32>>>(pred, target, out);
}

// round 5
// speedup vs baseline: 1.1705x; 1.1281x over previous
#include <cuda_runtime.h>

#define N_ROWS    65536
#define N_CLASSES 1000
#define N_F4      250          // 1000 / 4
#define EPS_F     1e-9f
#define NORM_FAC  0.1f
#define WARPS_PER_BLOCK 10     // 320 threads -> 5 CTAs/SM @40regs = 50 warps/SM
#define N_BLOCKS  ((N_ROWS + WARPS_PER_BLOCK - 1) / WARPS_PER_BLOCK)  // 6554

__device__ float        g_acc   = 0.0f;
__device__ unsigned int g_count = 0;

__global__ __launch_bounds__(WARPS_PER_BLOCK * 32)
void cosine_loss_kernel(const float* __restrict__ pred,
                        const long long* __restrict__ target,
                        float* __restrict__ out) {
    const int warp = threadIdx.x >> 5;
    const int lane = threadIdx.x & 31;
    const int row  = blockIdx.x * WARPS_PER_BLOCK + warp;

    float contrib = 0.0f;

    if (row < N_ROWS) {
        const float4* __restrict__ rowp =
            reinterpret_cast<const float4*>(pred + (size_t)row * N_CLASSES);

        const int t = (int)target[row];
        const int t_f4   = t >> 2;
        const int t_comp = t & 3;

        // Front-batch ALL 8 loads (MLP=8). Out-of-range lanes clamp to index
        // 249 — same sector as lane 25's load, no extra DRAM traffic.
        float4 v[8];
        #pragma unroll
        for (int j = 0; j < 8; j++) {
            const int f4  = lane + 32 * j;
            const int f4c = min(f4, N_F4 - 1);
            v[j] = __ldcs(rowp + f4c);
        }

        float sumsq    = 0.0f;
        float gathered = 0.0f;

        #pragma unroll
        for (int j = 0; j < 8; j++) {
            const int f4 = lane + 32 * j;
            const float4 w = v[j];
            if (f4 < N_F4) {
                sumsq += w.x * w.x + w.y * w.y + w.z * w.z + w.w * w.w;
            }
            if (f4 == t_f4) {
                gathered = (t_comp == 0) ? w.x :
                           (t_comp == 1) ? w.y :
                           (t_comp == 2) ? w.z : w.w;
            }
        }

        #pragma unroll
        for (int off = 16; off > 0; off >>= 1) {
            sumsq    += __shfl_xor_sync(0xffffffffu, sumsq, off);
            gathered += __shfl_xor_sync(0xffffffffu, gathered, off);
        }

        const float norm = sqrtf(sumsq);
        const float d    = 1.0f - norm;
        contrib = (-gathered / (norm + EPS_F) + NORM_FAC * d * d)
                  * (1.0f / (float)N_ROWS);
    }

    __shared__ float s_partial[WARPS_PER_BLOCK];
    if (lane == 0) s_partial[warp] = contrib;
    __syncthreads();

    if (threadIdx.x == 0) {
        float acc = 0.0f;
        #pragma unroll
        for (int i = 0; i < WARPS_PER_BLOCK; i++) acc += s_partial[i];
        atomicAdd(&g_acc, acc);
        __threadfence();
        const unsigned int old = atomicAdd(&g_count, 1u);
        if (old == (unsigned int)(N_BLOCKS - 1)) {
            // last block: all prior g_acc adds are visible (each fenced
            // before its counter increment). Publish and reset for replay.
            *out    = g_acc;
            g_acc   = 0.0f;
            g_count = 0;
        }
    }
}

extern "C" void kernel_launch(void* const* d_in, const int* in_sizes, int n_in,
                              void* d_out, int out_size) {
    const float*     pred   = (const float*)d_in[0];
    const long long* target = (const long long*)d_in[1];
    float*           out    = (float*)d_out;

    cosine_loss_kernel<<<N_BLOCKS, WARPS_PER_BLOCK * 32>>>(pred, target, out);
}

// round 6
// speedup vs baseline: 1.2139x; 1.0371x over previous
#include <cuda_runtime.h>

#define N_ROWS    65536
#define N_CLASSES 1000
#define N_F4      250          // 1000 / 4
#define EPS_F     1e-9f
#define NORM_FAC  0.1f
#define WARPS_PER_BLOCK 8
#define N_BLOCKS  (N_ROWS / WARPS_PER_BLOCK)   // 8192

__device__ float        g_acc   = 0.0f;
__device__ unsigned int g_count = 0;

__global__ __launch_bounds__(WARPS_PER_BLOCK * 32, 6)
void cosine_loss_kernel(const float* __restrict__ pred,
                        const long long* __restrict__ target,
                        float* __restrict__ out) {
    const int warp = threadIdx.x >> 5;
    const int lane = threadIdx.x & 31;
    const int row  = blockIdx.x * WARPS_PER_BLOCK + warp;

    const float4* __restrict__ rowp =
        reinterpret_cast<const float4*>(pred + (size_t)row * N_CLASSES);

    const int t = (int)target[row];
    const int t_f4   = t >> 2;
    const int t_comp = t & 3;

    // Front-batch ALL 8 loads (MLP=8). Out-of-range lanes (j==7, lane>=26)
    // clamp to index 249 — same sector as lane 25's load, no extra traffic.
    float4 v[8];
    #pragma unroll
    for (int j = 0; j < 8; j++) {
        const int f4  = lane + 32 * j;
        const int f4c = min(f4, N_F4 - 1);
        v[j] = __ldcs(rowp + f4c);
    }

    float sumsq    = 0.0f;
    float gathered = 0.0f;

    #pragma unroll
    for (int j = 0; j < 8; j++) {
        const int f4 = lane + 32 * j;
        const float4 w = v[j];
        if (f4 < N_F4) {
            sumsq += w.x * w.x + w.y * w.y + w.z * w.z + w.w * w.w;
        }
        if (f4 == t_f4) {
            gathered = (t_comp == 0) ? w.x :
                       (t_comp == 1) ? w.y :
                       (t_comp == 2) ? w.z : w.w;
        }
    }

    #pragma unroll
    for (int off = 16; off > 0; off >>= 1) {
        sumsq    += __shfl_xor_sync(0xffffffffu, sumsq, off);
        gathered += __shfl_xor_sync(0xffffffffu, gathered, off);
    }

    __shared__ float s_partial[WARPS_PER_BLOCK];
    if (lane == 0) {
        const float norm = sqrtf(sumsq);
        const float d    = 1.0f - norm;
        s_partial[warp] = (-gathered / (norm + EPS_F) + NORM_FAC * d * d)
                          * (1.0f / (float)N_ROWS);
    }
    __syncthreads();

    if (threadIdx.x == 0) {
        float acc = 0.0f;
        #pragma unroll
        for (int i = 0; i < WARPS_PER_BLOCK; i++) acc += s_partial[i];
        atomicAdd(&g_acc, acc);
        __threadfence();
        const unsigned int old = atomicAdd(&g_count, 1u);
        if (old == (unsigned int)(N_BLOCKS - 1)) {
            // last block: all prior g_acc adds are visible (each fenced
            // before its counter increment). Publish and reset for replay.
            *out    = g_acc;
            g_acc   = 0.0f;
            g_count = 0;
        }
    }
}

extern "C" void kernel_launch(void* const* d_in, const int* in_sizes, int n_in,
                              void* d_out, int out_size) {
    const float*     pred   = (const float*)d_in[0];
    const long long* target = (const long long*)d_in[1];
    float*           out    = (float*)d_out;

    cosine_loss_kernel<<<N_BLOCKS, WARPS_PER_BLOCK * 32>>>(pred, target, out);
}